// round 9
// baseline (speedup 1.0000x reference)
#include <cuda_runtime.h>

// CustomMetaPath2Vec: loss = mean(-log(sigmoid(pos_dots)+eps)) + mean(-log(1-sigmoid(neg_dots)+eps))
// 1.2M rows x 7 random gathers of 512B embedding rows = 4.3 GB gather-bound.
//
// R8 changes vs 536.7us version:
//  - double-buffered index prefetch: group g+1's 28-lane coalesced index load issues
//    before group g's compute -> idx DRAM latency fully hidden by scoreboard
//  - branch-free hot group loop (200000 % 4 == 0 and 1200000 % 4 == 0; generic
//    straddle/tail fallback kept but cold)
//  - finalize folded into the main kernel (threadfence + atomic counter, last block
//    reduces partials, writes out, resets counter) -> 1 launch total; ncu -s 5 -c 1
//    now must profile the main kernel
//
// NUMERICS (do not touch -> rel_err 0.0): s = 1.0f/(1.0f+expf(-x)) with accurate expf
// and true division; pos: -logf(s+1e-15f); neg: -logf(1.0f-s+1e-15f) (fp32
// cancellation + saturation exactly like the reference).

#define DIM      128
#define CTX      7
#define NCTX     6
#define EPSF     1e-15f
#define NTHREADS 256
#define NBLOCKS  (148 * 8)
#define GROUP    4          // rows per warp iteration (GROUP*CTX = 28 <= 32 lanes)

__device__ double       g_part_pos[NBLOCKS];
__device__ double       g_part_neg[NBLOCKS];
__device__ unsigned int g_done = 0;   // self-resetting completion counter

// Coalesced 28-lane index load for one group (assumes group does not straddle
// the pos/neg boundary; caller guarantees or uses the straddle path).
__device__ __forceinline__ int load_group_idx(
    const int* __restrict__ pos_rw, const int* __restrict__ neg_rw,
    long long r0, int pos_rows, int lane, int nlanes)
{
    const int* base = (r0 < (long long)pos_rows)
                        ? pos_rw + r0 * CTX
                        : neg_rw + (r0 - pos_rows) * CTX;
    return (lane < nlanes) ? __ldcg(base + lane) : 0;
}

__global__ __launch_bounds__(NTHREADS) void mp2v_kernel(
    const float* __restrict__ emb,
    const int*   __restrict__ pos_rw,
    const int*   __restrict__ neg_rw,
    int pos_rows, int neg_rows,
    float* __restrict__ out)
{
    const int lane = threadIdx.x & 31;
    const int wib  = threadIdx.x >> 5;
    const int wpb  = NTHREADS >> 5;

    const long long total   = (long long)pos_rows + neg_rows;
    const long long ngroups = (total + GROUP - 1) / GROUP;
    const long long gstride = (long long)gridDim.x * wpb;
    long long gidx          = (long long)blockIdx.x * wpb + wib;

    // Hot path requires: no group straddles the pos/neg boundary and no partial
    // tail group. True for the dataset (200000 % 4 == 0, 1200000 % 4 == 0).
    const bool uniform = ((pos_rows % GROUP) == 0) && ((total % GROUP) == 0);

    float accp = 0.0f, accn = 0.0f;

    if (uniform) {
        // Prime the index pipeline.
        int idx_cur = (gidx < ngroups)
            ? load_group_idx(pos_rw, neg_rw, gidx * GROUP, pos_rows, lane, GROUP * CTX)
            : 0;

        for (long long g = gidx; g < ngroups; g += gstride) {
            // Prefetch next group's indices NOW; consumed next iteration.
            const long long gn = g + gstride;
            int idx_nxt = (gn < ngroups)
                ? load_group_idx(pos_rw, neg_rw, gn * GROUP, pos_rows, lane, GROUP * CTX)
                : 0;

            const long long r0  = g * GROUP;
            const bool is_pos   = (r0 < (long long)pos_rows);  // uniform over group

            #pragma unroll
            for (int r = 0; r < GROUP; r++) {
                const int i0 = __shfl_sync(0xffffffffu, idx_cur, r * CTX);
                float4 h = __ldcg((const float4*)(emb + (long long)i0 * DIM) + lane);

                float4 cv[NCTX];
                #pragma unroll
                for (int j = 0; j < NCTX; j++) {
                    const int ij = __shfl_sync(0xffffffffu, idx_cur, r * CTX + j + 1);
                    cv[j] = __ldcg((const float4*)(emb + (long long)ij * DIM) + lane);
                }

                float p[NCTX];
                #pragma unroll
                for (int j = 0; j < NCTX; j++) {
                    float d = h.x * cv[j].x;
                    d = fmaf(h.y, cv[j].y, d);
                    d = fmaf(h.z, cv[j].z, d);
                    d = fmaf(h.w, cv[j].w, d);
                    p[j] = d;
                }

                // Butterfly reduce, 6 independent chains (ILP over SHFL latency).
                #pragma unroll
                for (int off = 16; off > 0; off >>= 1) {
                    #pragma unroll
                    for (int j = 0; j < NCTX; j++)
                        p[j] += __shfl_xor_sync(0xffffffffu, p[j], off);
                }

                // Lane j takes dot j; 6-way parallel exp/div/log.
                float x = p[0];
                #pragma unroll
                for (int j = 1; j < NCTX; j++)
                    if (lane == j) x = p[j];

                if (lane < NCTX) {
                    const float s = 1.0f / (1.0f + expf(-x));
                    if (is_pos) accp += -logf(s + EPSF);
                    else        accn += -logf(1.0f - s + EPSF);
                }
            }
            idx_cur = idx_nxt;
        }
    } else {
        // Cold generic path: per-row indexing, handles straddle + tail.
        for (long long g = gidx; g < ngroups; g += gstride) {
            const long long r0 = g * GROUP;
            const int nrows = (int)((total - r0 < GROUP) ? (total - r0) : GROUP);
            int myidx = 0;
            if (lane < nrows * CTX) {
                const int rr = lane / CTX, cc = lane % CTX;
                const long long row = r0 + rr;
                myidx = (row < (long long)pos_rows)
                          ? pos_rw[row * CTX + cc]
                          : neg_rw[(row - pos_rows) * CTX + cc];
            }
            for (int r = 0; r < nrows; r++) {
                const bool is_pos = (r0 + r) < (long long)pos_rows;
                const int i0 = __shfl_sync(0xffffffffu, myidx, r * CTX);
                float4 h = __ldcg((const float4*)(emb + (long long)i0 * DIM) + lane);
                float4 cv[NCTX];
                #pragma unroll
                for (int j = 0; j < NCTX; j++) {
                    const int ij = __shfl_sync(0xffffffffu, myidx, r * CTX + j + 1);
                    cv[j] = __ldcg((const float4*)(emb + (long long)ij * DIM) + lane);
                }
                float p[NCTX];
                #pragma unroll
                for (int j = 0; j < NCTX; j++) {
                    float d = h.x * cv[j].x;
                    d = fmaf(h.y, cv[j].y, d);
                    d = fmaf(h.z, cv[j].z, d);
                    d = fmaf(h.w, cv[j].w, d);
                    p[j] = d;
                }
                #pragma unroll
                for (int off = 16; off > 0; off >>= 1) {
                    #pragma unroll
                    for (int j = 0; j < NCTX; j++)
                        p[j] += __shfl_xor_sync(0xffffffffu, p[j], off);
                }
                float x = p[0];
                #pragma unroll
                for (int j = 1; j < NCTX; j++)
                    if (lane == j) x = p[j];
                if (lane < NCTX) {
                    const float s = 1.0f / (1.0f + expf(-x));
                    if (is_pos) accp += -logf(s + EPSF);
                    else        accn += -logf(1.0f - s + EPSF);
                }
            }
        }
    }

    // ---- Block reduction -> per-CTA partial slot ----
    double dp = (double)accp, dn = (double)accn;
    #pragma unroll
    for (int off = 16; off > 0; off >>= 1) {
        dp += __shfl_xor_sync(0xffffffffu, dp, off);
        dn += __shfl_xor_sync(0xffffffffu, dn, off);
    }

    __shared__ double s_pos[NTHREADS >> 5], s_neg[NTHREADS >> 5];
    __shared__ bool   am_last;
    if (lane == 0) { s_pos[wib] = dp; s_neg[wib] = dn; }
    __syncthreads();
    if (threadIdx.x == 0) {
        double sp = 0.0, sn = 0.0;
        #pragma unroll
        for (int w = 0; w < (NTHREADS >> 5); w++) { sp += s_pos[w]; sn += s_neg[w]; }
        g_part_pos[blockIdx.x] = sp;
        g_part_neg[blockIdx.x] = sn;
        __threadfence();
        const unsigned t = atomicAdd(&g_done, 1u);
        am_last = (t == (unsigned)(gridDim.x - 1));
    }
    __syncthreads();

    // ---- Last CTA: final reduction + output + counter reset ----
    if (am_last) {
        __threadfence();  // acquire partials from all CTAs
        double a = 0.0, b = 0.0;
        for (int i = threadIdx.x; i < (int)gridDim.x; i += NTHREADS) {
            a += g_part_pos[i];
            b += g_part_neg[i];
        }
        #pragma unroll
        for (int off = 16; off > 0; off >>= 1) {
            a += __shfl_xor_sync(0xffffffffu, a, off);
            b += __shfl_xor_sync(0xffffffffu, b, off);
        }
        if (lane == 0) { s_pos[wib] = a; s_neg[wib] = b; }
        __syncthreads();
        if (threadIdx.x == 0) {
            double sp = 0.0, sn = 0.0;
            #pragma unroll
            for (int w = 0; w < (NTHREADS >> 5); w++) { sp += s_pos[w]; sn += s_neg[w]; }
            const double n_pos_terms = (double)((long long)pos_rows * NCTX);
            const double n_neg_terms = (double)((long long)neg_rows * NCTX);
            out[0] = (float)(sp / n_pos_terms + sn / n_neg_terms);
            g_done = 0;   // self-reset for next graph replay
        }
    }
}

extern "C" void kernel_launch(void* const* d_in, const int* in_sizes, int n_in,
                              void* d_out, int out_size) {
    const float* emb    = (const float*)d_in[0];
    const int*   pos_rw = (const int*)d_in[1];
    const int*   neg_rw = (const int*)d_in[2];
    float*       out    = (float*)d_out;

    const int pos_rows = in_sizes[1] / CTX;   // 200000
    const int neg_rows = in_sizes[2] / CTX;   // 1000000

    mp2v_kernel<<<NBLOCKS, NTHREADS>>>(emb, pos_rw, neg_rw, pos_rows, neg_rows, out);
}